// round 6
// baseline (speedup 1.0000x reference)
#include <cuda_runtime.h>

// Input:  image [256, 384, 384] float32   (i, j, c')
// Output: out   [1, 384, 320, 512] float32 (j, a, c)
//
// c: 384 -> 512 (x4/3): outputs 4k..4k+3 <- inputs 3k-1..3k+3,
//    fixed weights {0.875, 0.625, 0.375, 0.125}
// a: 256 -> 320 (x5/4): outputs 5m..5m+4 <- rows 4m-1..4m+4,
//    fixed weights {0.9, 0.7, 0.5, 0.3, 0.1}
// Boundary clamps degenerate (x[i]==x[i+1]) so fixed weights hold everywhere.
//
// R6: smem-staged, 4 a-groups per block (reread 18/16 = 1.125x vs 1.25x):
//   Phase 1: 18 input rows (16*m4-1 .. 16*m4+16, clamped) staged coalesced.
//   Phase 2: 512 threads = 128 c-groups x 4 a-groups; taps from smem
//            (stride-3 cols, conflict-free), 5 float4 streaming stores each.

#define D0 256
#define D1 384
#define D2 384
#define S0 320
#define S1 384
#define S2 512

#define ROWS_SM 18
#define THREADS 512

__global__ __launch_bounds__(THREADS)
void resize3d_kernel(const float* __restrict__ in, float* __restrict__ out) {
    __shared__ float sm[ROWS_SM][D2];

    const int tid = threadIdx.x;
    const int m4 = blockIdx.x;      // 0..15: quad of a-groups
    const int j  = blockIdx.y;      // 0..383

    // ---- Phase 1: coalesced float4 staging of 18 input rows ----
    // slot t <- input row clamp(16*m4 - 1 + t, 0, 255)
    {
        const int base_row = 16 * m4 - 1;
        #pragma unroll
        for (int idx = tid; idx < ROWS_SM * (D2 / 4); idx += THREADS) {
            int t = idx / (D2 / 4);
            int q = idx % (D2 / 4);
            int g = min(max(base_row + t, 0), D0 - 1);
            const float4* rp = (const float4*)(in + ((size_t)g * D1 + j) * D2);
            ((float4*)sm[t])[q] = __ldg(rp + q);
        }
    }
    __syncthreads();

    // ---- Phase 2: interpolate ----
    const int k = tid & 127;        // c-group 0..127 -> output cols 4k..4k+3
    const int y = tid >> 7;         // 0..3: a-group within the quad
    const int m = 4 * m4 + y;

    const int col0 = max(3 * k - 1, 0);
    const int col1 = 3 * k;
    const int col4 = min(3 * k + 3, D2 - 1);
    const int t0 = 4 * y;           // smem slots t0..t0+5 = rows 4m-1..4m+4

    float l[6][4];
    #pragma unroll
    for (int t = 0; t < 6; ++t) {
        const float* r = sm[t0 + t];
        float x0 = r[col0];
        float x1 = r[col1];
        float x2 = r[col1 + 1];
        float x3 = r[col1 + 2];
        float x4 = r[col4];
        l[t][0] = x0 + 0.875f * (x1 - x0);
        l[t][1] = x1 + 0.625f * (x2 - x1);
        l[t][2] = x2 + 0.375f * (x3 - x2);
        l[t][3] = x3 + 0.125f * (x4 - x3);
    }

    float4* op = (float4*)(out + ((size_t)j * S0 + 5 * m) * S2 + 4 * k);
    const float wa[5] = {0.9f, 0.7f, 0.5f, 0.3f, 0.1f};

    #pragma unroll
    for (int s = 0; s < 5; ++s) {
        float w = wa[s];
        float4 o;
        o.x = l[s][0] + w * (l[s + 1][0] - l[s][0]);
        o.y = l[s][1] + w * (l[s + 1][1] - l[s][1]);
        o.z = l[s][2] + w * (l[s + 1][2] - l[s][2]);
        o.w = l[s][3] + w * (l[s + 1][3] - l[s][3]);
        __stcs(op, o);
        op += S2 / 4;
    }
}

extern "C" void kernel_launch(void* const* d_in, const int* in_sizes, int n_in,
                              void* d_out, int out_size) {
    (void)in_sizes; (void)n_in; (void)out_size;
    const float* in = (const float*)d_in[0];
    float* out = (float*)d_out;

    dim3 grid(S0 / 5 / 4, S1, 1);   // (a-group quads fastest, j)
    dim3 block(THREADS, 1, 1);
    resize3d_kernel<<<grid, block>>>(in, out);
}